// round 10
// baseline (speedup 1.0000x reference)
#include <cuda_runtime.h>
#include <cuda_fp16.h>
#include <cstdint>

#define NHEADS 24

// ================= prepacked fp16 KV (glued canvas, roped K) =================
__device__ __half g_kpk[(long)NHEADS * 30720 * 128];   // [head][g][d]
__device__ __half g_vpk[(long)NHEADS * 30720 * 128];

// ================= RoPE tables =================
__device__ float2 g_rope_t[12 * 8];
__device__ float2 g_rope_h[40 * 28];
__device__ float2 g_rope_w[64 * 28];

__global__ void rope_init_kernel() {
    int idx = blockIdx.x * blockDim.x + threadIdx.x;
    if (idx < 96) {
        int p = idx >> 3, j = idx & 7;
        float ang = (float)p * exp2f(-(float)j);
        g_rope_t[idx] = make_float2(cosf(ang), sinf(ang));
    } else if (idx < 96 + 1120) {
        int r = idx - 96, i = r / 28, j = r % 28;
        float ang = (float)(i - 8) * exp2f(-8.0f * (float)j / 28.0f);
        g_rope_h[r] = make_float2(cosf(ang), sinf(ang));
    } else if (idx < 96 + 1120 + 1792) {
        int r = idx - 96 - 1120, i = r / 28, j = r % 28;
        float ang = (float)(i - 8) * exp2f(-8.0f * (float)j / 28.0f);
        g_rope_w[r] = make_float2(cosf(ang), sinf(ang));
    }
}

__device__ __forceinline__ float2 rope_pair(int pt, int ih, int iw, int j) {
    if (j < 8)  return g_rope_t[pt * 8 + j];
    if (j < 36) return g_rope_h[ih * 28 + (j - 8)];
    return g_rope_w[iw * 28 + (j - 36)];
}

__device__ __forceinline__ uint32_t packh2(float lo, float hi) {
    __half2 h = __floats2half2_rn(lo, hi);
    return *(uint32_t*)&h;
}

// ---- coalesced prepack: thread = (glued row, 4-dim slice) ----
__global__ void prepack_kv2(const float* __restrict__ k, const float* __restrict__ v) {
    const long idx = (long)blockIdx.x * 256 + threadIdx.x;   // row*32 + d4
    if (idx >= (long)NHEADS * 30720 * 32) return;
    const int d4 = (int)(idx & 31);
    const long row = idx >> 5;                 // row = g*24 + head (input-coalesced order)
    const int head = (int)(row % 24);
    const int g = (int)(row / 24);
    const int t = g / 2560, rem = g % 2560, hg = rem >> 6, wg = rem & 63;
    int hh = hg - 8; if (hh < 0) hh += 24; if (hh >= 24) hh -= 24;
    int ww = wg - 8; if (ww < 0) ww += 48; if (ww >= 48) ww -= 48;
    const long l = (long)(t * 24 + hh) * 48 + ww;
    const int d = d4 * 4;
    float4 x = *(const float4*)(k + (l * NHEADS + head) * 128 + d);
    float2 r0 = rope_pair(t, hg, wg, d >> 1);
    float2 r1 = rope_pair(t, hg, wg, (d >> 1) + 1);
    uint2 y;
    y.x = packh2(x.x * r0.x - x.y * r0.y, x.y * r0.x + x.x * r0.y);
    y.y = packh2(x.z * r1.x - x.w * r1.y, x.w * r1.x + x.z * r1.y);
    *(uint2*)((char*)(g_kpk + ((long)head * 30720 + g) * 128) + d * 2) = y;
    float4 xv = *(const float4*)(v + (l * NHEADS + head) * 128 + d);
    uint2 yv; yv.x = packh2(xv.x, xv.y); yv.y = packh2(xv.z, xv.w);
    *(uint2*)((char*)(g_vpk + ((long)head * 30720 + g) * 128) + d * 2) = yv;
}

// ================= main-kernel helpers =================
__device__ __forceinline__ uint32_t smem_u32(const void* p) {
    uint32_t a;
    asm("{ .reg .u64 t; cvta.to.shared.u64 t, %1; cvt.u32.u64 %0, t; }" : "=r"(a) : "l"(p));
    return a;
}
__device__ __forceinline__ uint32_t cvt_ex2(float lo, float hi) {
    uint32_t h, r;
    asm("cvt.rn.f16x2.f32 %0, %1, %2;" : "=r"(h) : "f"(hi), "f"(lo));
    asm("ex2.approx.f16x2 %0, %1;" : "=r"(r) : "r"(h));
    return r;
}
__device__ __forceinline__ void cp16(uint32_t dst, const void* src) {
    asm volatile("cp.async.cg.shared.global [%0], [%1], 16;" :: "r"(dst), "l"(src));
}
#define CP_COMMIT() asm volatile("cp.async.commit_group;" ::: "memory")
#define CP_WAIT(n)  asm volatile("cp.async.wait_group %0;" :: "n"(n) : "memory")

__device__ __forceinline__ void ldsm_x4(uint32_t& r0, uint32_t& r1, uint32_t& r2,
                                        uint32_t& r3, uint32_t addr) {
    asm volatile("ldmatrix.sync.aligned.m8n8.x4.shared.b16 {%0,%1,%2,%3}, [%4];"
        : "=r"(r0), "=r"(r1), "=r"(r2), "=r"(r3) : "r"(addr));
}
__device__ __forceinline__ void ldsm_x4t(uint32_t& r0, uint32_t& r1, uint32_t& r2,
                                         uint32_t& r3, uint32_t addr) {
    asm volatile("ldmatrix.sync.aligned.m8n8.x4.trans.shared.b16 {%0,%1,%2,%3}, [%4];"
        : "=r"(r0), "=r"(r1), "=r"(r2), "=r"(r3) : "r"(addr));
}
__device__ __forceinline__ void mma_f16(float* c,
                                        uint32_t a0, uint32_t a1, uint32_t a2, uint32_t a3,
                                        uint32_t b0, uint32_t b1) {
    asm volatile(
        "mma.sync.aligned.m16n8k16.row.col.f32.f16.f16.f32 "
        "{%0,%1,%2,%3}, {%4,%5,%6,%7}, {%8,%9}, {%0,%1,%2,%3};\n"
        : "+f"(c[0]), "+f"(c[1]), "+f"(c[2]), "+f"(c[3])
        : "r"(a0), "r"(a1), "r"(a2), "r"(a3), "r"(b0), "r"(b1));
}

// ================= smem layout (bytes) =================
#define PITCH  272u
#define QS_B   0u            // 256 x 272 = 69632
#define KS_B   69632u        // 2 x (128 x 272) = 69632
#define VS_B   139264u       // 2 x (128 x 272)
#define KVSTRIDE 34816u
#define SMEM_TOTAL 208896u

#define ONESH2 0x3C003C00u

// stage one 128-key tile (2 t-slices of one kv block) via cp.async
// 256 threads: thread = (row 0..127, 128B half)
__device__ __forceinline__ void stage_async(uint32_t kd_base, uint32_t vd_base,
                                            const __half* kbase, const __half* vbase,
                                            int qt1, int qt2, int ci, int tid) {
    const int blk = ci >> 1, tpair = (ci & 1) * 2;
    const int r = tid >> 1, hb = tid & 1;             // row in tile, 128B half
    const int c4 = tpair + (r >> 6);
    const int rr = r & 63;
    const int t = (blk / 9) * 4 + c4;
    const int hg = (qt1 + (blk / 3) % 3) * 8 + (rr >> 3);
    const int wg = (qt2 + blk % 3) * 8 + (rr & 7);
    const long g = (long)(t * 40 + hg) * 64 + wg;
    const char* ks = (const char*)(kbase + g * 128) + hb * 128;
    const char* vs = (const char*)(vbase + g * 128) + hb * 128;
    const uint32_t ka = kd_base + (uint32_t)r * PITCH + (uint32_t)hb * 128u;
    const uint32_t va = vd_base + (uint32_t)r * PITCH + (uint32_t)hb * 128u;
    #pragma unroll
    for (int f = 0; f < 8; ++f) cp16(ka + f * 16u, ks + f * 16);
    #pragma unroll
    for (int f = 0; f < 8; ++f) cp16(va + f * 16u, vs + f * 16);
}

__global__ __launch_bounds__(256, 1)
void sta_attn7(const float* __restrict__ q, float* __restrict__ out) {
    extern __shared__ char smem[];
    const uint32_t sb = smem_u32(smem);
    const int tid = threadIdx.x, warp = tid >> 5, lane = tid & 31;
    const int head = blockIdx.y;
    const int qb = blockIdx.x;
    const int qt0 = qb / 18, qt1 = (qb / 6) % 3, qt2 = qb % 6;
    const float QSCALE = 0.088388347648318447f * 1.4426950408889634f;
    const __half* kbase = g_kpk + (long)head * 30720 * 128;
    const __half* vbase = g_vpk + (long)head * 30720 * 128;

    // ---- stage Q inline (rope + scale -> fp16), 1 row/thread ----
    {
        const int r = tid;
        const int a = r >> 6, b = (r >> 3) & 7, c = r & 7;
        const int t = qt0 * 4 + a, hh = qt1 * 8 + b, ww = qt2 * 8 + c;
        const long l = ((long)(t * 24 + hh)) * 48 + ww;
        const float* src = q + (l * NHEADS + head) * 128;
        const int ih = hh + 8, iw = ww + 8;
        char* qrow = smem + QS_B + (uint32_t)r * PITCH;
        #pragma unroll
        for (int f = 0; f < 32; ++f) {
            const int d = f * 4;
            float4 x = *(const float4*)(src + d);
            float2 r0 = rope_pair(t, ih, iw, d >> 1);
            float2 r1 = rope_pair(t, ih, iw, (d >> 1) + 1);
            uint2 y;
            y.x = packh2((x.x * r0.x - x.y * r0.y) * QSCALE,
                         (x.y * r0.x + x.x * r0.y) * QSCALE);
            y.y = packh2((x.z * r1.x - x.w * r1.y) * QSCALE,
                         (x.w * r1.x + x.z * r1.y) * QSCALE);
            *(uint2*)(qrow + d * 2) = y;
        }
    }
    // ---- prefetch tile 0 ----
    stage_async(sb + KS_B, sb + VS_B, kbase, vbase, qt1, qt2, 0, tid);
    CP_COMMIT();
    CP_WAIT(0);
    __syncthreads();

    // accumulators: warp owns q-rows [32*warp, 32*warp+32)
    float o0[16][4], o1[16][4];
    #pragma unroll
    for (int i = 0; i < 16; ++i) {
        o0[i][0]=0.f; o0[i][1]=0.f; o0[i][2]=0.f; o0[i][3]=0.f;
        o1[i][0]=0.f; o1[i][1]=0.f; o1[i][2]=0.f; o1[i][3]=0.f;
    }
    float lf0[4] = {0.f,0.f,0.f,0.f}, lf1[4] = {0.f,0.f,0.f,0.f};

    const uint32_t qb0 = sb + QS_B +
        (uint32_t)(warp * 32 + (lane & 15)) * PITCH + (uint32_t)(lane >> 4) * 16u;
    const uint32_t qb1 = qb0 + 16u * PITCH;
    const uint32_t kRow = (uint32_t)((((lane >> 4) & 1) * 8 + (lane & 7)) * PITCH
                                     + ((lane >> 3) & 1) * 16);
    const uint32_t vRow = (uint32_t)(((((lane >> 3) & 1) * 8) + (lane & 7)) * PITCH
                                     + (lane >> 4) * 16);

    #pragma unroll 1
    for (int i = 0; i < 54; ++i) {
        const uint32_t mr = (uint32_t)(i & 1) * KVSTRIDE;

        // prefetch tile i+1 into the other buffer (overlaps this tile's compute)
        if (i < 53) {
            const uint32_t mw = (uint32_t)((i + 1) & 1) * KVSTRIDE;
            stage_async(sb + KS_B + mw, sb + VS_B + mw, kbase, vbase, qt1, qt2, i + 1, tid);
            CP_COMMIT();
        }

        #pragma unroll
        for (int sub = 0; sub < 2; ++sub) {
            const uint32_t ksb = sb + KS_B + mr + (uint32_t)sub * (64u * PITCH) + kRow;
            const uint32_t vsb = sb + VS_B + mr + (uint32_t)sub * (64u * PITCH) + vRow;

            // ---- S = Q x K^T : 32 rows x 64 keys, k=128 ----
            float s0[8][4], s1[8][4];
            #pragma unroll
            for (int nt = 0; nt < 8; ++nt) {
                s0[nt][0]=0.f; s0[nt][1]=0.f; s0[nt][2]=0.f; s0[nt][3]=0.f;
                s1[nt][0]=0.f; s1[nt][1]=0.f; s1[nt][2]=0.f; s1[nt][3]=0.f;
            }
            #pragma unroll
            for (int kk = 0; kk < 8; ++kk) {
                uint32_t q0[4], q1[4];
                ldsm_x4(q0[0], q0[1], q0[2], q0[3], qb0 + (uint32_t)kk * 32u);
                ldsm_x4(q1[0], q1[1], q1[2], q1[3], qb1 + (uint32_t)kk * 32u);
                #pragma unroll
                for (int n2 = 0; n2 < 4; ++n2) {
                    uint32_t b0, b1, b2, b3;
                    ldsm_x4(b0, b1, b2, b3,
                            ksb + (uint32_t)n2 * (16u * PITCH) + (uint32_t)kk * 32u);
                    mma_f16(s0[2*n2],   q0[0], q0[1], q0[2], q0[3], b0, b1);
                    mma_f16(s0[2*n2+1], q0[0], q0[1], q0[2], q0[3], b2, b3);
                    mma_f16(s1[2*n2],   q1[0], q1[1], q1[2], q1[3], b0, b1);
                    mma_f16(s1[2*n2+1], q1[0], q1[1], q1[2], q1[3], b2, b3);
                }
            }

            // ---- softmax in f16x2; accumulator layout == A-fragment layout ----
            uint32_t pa0[4][4], pa1[4][4];
            #pragma unroll
            for (int nt = 0; nt < 8; ++nt) {
                pa0[nt >> 1][(nt & 1) * 2 + 0] = cvt_ex2(s0[nt][0], s0[nt][1]);
                pa0[nt >> 1][(nt & 1) * 2 + 1] = cvt_ex2(s0[nt][2], s0[nt][3]);
                pa1[nt >> 1][(nt & 1) * 2 + 0] = cvt_ex2(s1[nt][0], s1[nt][1]);
                pa1[nt >> 1][(nt & 1) * 2 + 1] = cvt_ex2(s1[nt][2], s1[nt][3]);
            }
            // row-sums via ones-MMA
            #pragma unroll
            for (int kk = 0; kk < 4; ++kk) {
                mma_f16(lf0, pa0[kk][0], pa0[kk][1], pa0[kk][2], pa0[kk][3], ONESH2, ONESH2);
                mma_f16(lf1, pa1[kk][0], pa1[kk][1], pa1[kk][2], pa1[kk][3], ONESH2, ONESH2);
            }

            // ---- O += P x V ----
            #pragma unroll
            for (int kk = 0; kk < 4; ++kk) {
                #pragma unroll
                for (int n2 = 0; n2 < 8; ++n2) {
                    uint32_t b0, b1, b2, b3;
                    ldsm_x4t(b0, b1, b2, b3,
                             vsb + (uint32_t)kk * (16u * PITCH) + (uint32_t)n2 * 32u);
                    mma_f16(o0[2*n2],   pa0[kk][0], pa0[kk][1], pa0[kk][2], pa0[kk][3], b0, b1);
                    mma_f16(o0[2*n2+1], pa0[kk][0], pa0[kk][1], pa0[kk][2], pa0[kk][3], b2, b3);
                    mma_f16(o1[2*n2],   pa1[kk][0], pa1[kk][1], pa1[kk][2], pa1[kk][3], b0, b1);
                    mma_f16(o1[2*n2+1], pa1[kk][0], pa1[kk][1], pa1[kk][2], pa1[kk][3], b2, b3);
                }
            }
        }

        if (i < 53) CP_WAIT(0);   // tile i+1 landed
        __syncthreads();          // all warps done with buffer i&1
    }

    // ---- epilogue ----
    const int g_ = lane >> 2, tig = lane & 3;
    #pragma unroll
    for (int hf = 0; hf < 2; ++hf) {
        const float inv0 = 1.0f / (hf ? lf1[0] : lf0[0]);
        const float inv1 = 1.0f / (hf ? lf1[2] : lf0[2]);
        #pragma unroll
        for (int rr = 0; rr < 2; ++rr) {
            const int qi = warp * 32 + hf * 16 + g_ + rr * 8;
            const int a = qi >> 6, b = (qi >> 3) & 7, c = qi & 7;
            const int t = qt0 * 4 + a, hh = qt1 * 8 + b, ww = qt2 * 8 + c;
            const long l = ((long)(t * 24 + hh)) * 48 + ww;
            float* dst = out + (l * NHEADS + head) * 128;
            const float inv = rr ? inv1 : inv0;
            #pragma unroll
            for (int nt = 0; nt < 16; ++nt) {
                float x0 = (hf ? o1 : o0)[nt][rr * 2 + 0] * inv;
                float x1 = (hf ? o1 : o0)[nt][rr * 2 + 1] * inv;
                *(float2*)(dst + nt * 8 + 2 * tig) = make_float2(x0, x1);
            }
        }
    }
}

extern "C" void kernel_launch(void* const* d_in, const int* in_sizes, int n_in,
                              void* d_out, int out_size) {
    const float* q = (const float*)d_in[0];
    const float* k = (const float*)d_in[1];
    const float* v = (const float*)d_in[2];
    float* out = (float*)d_out;

    rope_init_kernel<<<12, 256>>>();
    prepack_kv2<<<(int)(((long)NHEADS * 30720 * 32 + 255) / 256), 256>>>(k, v);

    cudaFuncSetAttribute(sta_attn7, cudaFuncAttributeMaxDynamicSharedMemorySize,
                         (int)SMEM_TOTAL);
    dim3 grid(54, NHEADS);
    sta_attn7<<<grid, 256, SMEM_TOTAL>>>(q, out);
}

// round 11
// speedup vs baseline: 1.3033x; 1.3033x over previous
#include <cuda_runtime.h>
#include <cuda_fp16.h>
#include <cstdint>

#define NHEADS 24

// ================= prepacked fp16 buffers =================
__device__ __half g_qpk[(long)NHEADS * 13824 * 128];   // roped+scaled Q [head][l][d]
__device__ __half g_kpk[(long)NHEADS * 30720 * 128];   // roped K, glued canvas [head][g][d]
__device__ __half g_vpk[(long)NHEADS * 30720 * 128];   // V, glued canvas

// ================= RoPE tables =================
__device__ float2 g_rope_t[12 * 8];
__device__ float2 g_rope_h[40 * 28];
__device__ float2 g_rope_w[64 * 28];

__global__ void rope_init_kernel() {
    int idx = blockIdx.x * blockDim.x + threadIdx.x;
    if (idx < 96) {
        int p = idx >> 3, j = idx & 7;
        float ang = (float)p * exp2f(-(float)j);
        g_rope_t[idx] = make_float2(cosf(ang), sinf(ang));
    } else if (idx < 96 + 1120) {
        int r = idx - 96, i = r / 28, j = r % 28;
        float ang = (float)(i - 8) * exp2f(-8.0f * (float)j / 28.0f);
        g_rope_h[r] = make_float2(cosf(ang), sinf(ang));
    } else if (idx < 96 + 1120 + 1792) {
        int r = idx - 96 - 1120, i = r / 28, j = r % 28;
        float ang = (float)(i - 8) * exp2f(-8.0f * (float)j / 28.0f);
        g_rope_w[r] = make_float2(cosf(ang), sinf(ang));
    }
}

__device__ __forceinline__ float2 rope_pair(int pt, int ih, int iw, int j) {
    if (j < 8)  return g_rope_t[pt * 8 + j];
    if (j < 36) return g_rope_h[ih * 28 + (j - 8)];
    return g_rope_w[iw * 28 + (j - 36)];
}

__device__ __forceinline__ uint32_t packh2(float lo, float hi) {
    __half2 h = __floats2half2_rn(lo, hi);
    return *(uint32_t*)&h;
}

// ---- coalesced prepack KV: thread = (glued row, 4-dim slice) ----
__global__ void prepack_kv2(const float* __restrict__ k, const float* __restrict__ v) {
    const long idx = (long)blockIdx.x * 256 + threadIdx.x;   // row*32 + d4
    if (idx >= (long)NHEADS * 30720 * 32) return;
    const int d4 = (int)(idx & 31);
    const long row = idx >> 5;
    const int head = (int)(row % 24);
    const int g = (int)(row / 24);
    const int t = g / 2560, rem = g % 2560, hg = rem >> 6, wg = rem & 63;
    int hh = hg - 8; if (hh < 0) hh += 24; if (hh >= 24) hh -= 24;
    int ww = wg - 8; if (ww < 0) ww += 48; if (ww >= 48) ww -= 48;
    const long l = (long)(t * 24 + hh) * 48 + ww;
    const int d = d4 * 4;
    float4 x = *(const float4*)(k + (l * NHEADS + head) * 128 + d);
    float2 r0 = rope_pair(t, hg, wg, d >> 1);
    float2 r1 = rope_pair(t, hg, wg, (d >> 1) + 1);
    uint2 y;
    y.x = packh2(x.x * r0.x - x.y * r0.y, x.y * r0.x + x.x * r0.y);
    y.y = packh2(x.z * r1.x - x.w * r1.y, x.w * r1.x + x.z * r1.y);
    *(uint2*)((char*)(g_kpk + ((long)head * 30720 + g) * 128) + d * 2) = y;
    float4 xv = *(const float4*)(v + (l * NHEADS + head) * 128 + d);
    uint2 yv; yv.x = packh2(xv.x, xv.y); yv.y = packh2(xv.z, xv.w);
    *(uint2*)((char*)(g_vpk + ((long)head * 30720 + g) * 128) + d * 2) = yv;
}

// ---- coalesced prepack Q: thread = (canvas row, 4-dim slice) ----
__global__ void prepack_q2(const float* __restrict__ q) {
    const long idx = (long)blockIdx.x * 256 + threadIdx.x;   // row*32 + d4
    if (idx >= (long)NHEADS * 13824 * 32) return;
    const int d4 = (int)(idx & 31);
    const long row = idx >> 5;                 // row = l*24 + head (input order)
    const int head = (int)(row % 24);
    const int l = (int)(row / 24);
    const int t = l / 1152, rem = l % 1152, hh = rem / 48, ww = rem % 48;
    const float QSCALE = 0.088388347648318447f * 1.4426950408889634f;
    const int d = d4 * 4;
    float4 x = *(const float4*)(q + ((long)l * NHEADS + head) * 128 + d);
    float2 r0 = rope_pair(t, hh + 8, ww + 8, d >> 1);
    float2 r1 = rope_pair(t, hh + 8, ww + 8, (d >> 1) + 1);
    uint2 y;
    y.x = packh2((x.x * r0.x - x.y * r0.y) * QSCALE, (x.y * r0.x + x.x * r0.y) * QSCALE);
    y.y = packh2((x.z * r1.x - x.w * r1.y) * QSCALE, (x.w * r1.x + x.z * r1.y) * QSCALE);
    *(uint2*)((char*)(g_qpk + ((long)head * 13824 + l) * 128) + d * 2) = y;
}

// ================= main-kernel helpers =================
__device__ __forceinline__ uint32_t smem_u32(const void* p) {
    uint32_t a;
    asm("{ .reg .u64 t; cvta.to.shared.u64 t, %1; cvt.u32.u64 %0, t; }" : "=r"(a) : "l"(p));
    return a;
}
__device__ __forceinline__ uint32_t cvt_ex2(float lo, float hi) {
    uint32_t h, r;
    asm("cvt.rn.f16x2.f32 %0, %1, %2;" : "=r"(h) : "f"(hi), "f"(lo));
    asm("ex2.approx.f16x2 %0, %1;" : "=r"(r) : "r"(h));
    return r;
}
__device__ __forceinline__ void cp16(uint32_t dst, const void* src) {
    asm volatile("cp.async.cg.shared.global [%0], [%1], 16;" :: "r"(dst), "l"(src));
}
#define CP_COMMIT() asm volatile("cp.async.commit_group;" ::: "memory")
#define CP_WAIT(n)  asm volatile("cp.async.wait_group %0;" :: "n"(n) : "memory")

__device__ __forceinline__ void ldsm_x4(uint32_t& r0, uint32_t& r1, uint32_t& r2,
                                        uint32_t& r3, uint32_t addr) {
    asm volatile("ldmatrix.sync.aligned.m8n8.x4.shared.b16 {%0,%1,%2,%3}, [%4];"
        : "=r"(r0), "=r"(r1), "=r"(r2), "=r"(r3) : "r"(addr));
}
__device__ __forceinline__ void ldsm_x4t(uint32_t& r0, uint32_t& r1, uint32_t& r2,
                                         uint32_t& r3, uint32_t addr) {
    asm volatile("ldmatrix.sync.aligned.m8n8.x4.trans.shared.b16 {%0,%1,%2,%3}, [%4];"
        : "=r"(r0), "=r"(r1), "=r"(r2), "=r"(r3) : "r"(addr));
}
__device__ __forceinline__ void mma_f16(float* c,
                                        uint32_t a0, uint32_t a1, uint32_t a2, uint32_t a3,
                                        uint32_t b0, uint32_t b1) {
    asm volatile(
        "mma.sync.aligned.m16n8k16.row.col.f32.f16.f16.f32 "
        "{%0,%1,%2,%3}, {%4,%5,%6,%7}, {%8,%9}, {%0,%1,%2,%3};\n"
        : "+f"(c[0]), "+f"(c[1]), "+f"(c[2]), "+f"(c[3])
        : "r"(a0), "r"(a1), "r"(a2), "r"(a3), "r"(b0), "r"(b1));
}

// ================= smem layout (bytes) =================
#define PITCH  272u
#define QS_B   0u            // 256 x 272 = 69632
#define KS_B   69632u        // 3 x (64 x 272)
#define VS_B   121856u       // 3 x (64 x 272)
#define KVSTRIDE 17408u
#define SMEM_TOTAL 174080u

#define ONESH2 0x3C003C00u

// stage one 64-key chunk via cp.async: 4 threads/row, 64B each
__device__ __forceinline__ void stage_async(uint32_t kd_base, uint32_t vd_base,
                                            const __half* kbase, const __half* vbase,
                                            int qt1, int qt2, int ci, int tid) {
    const int blk = ci >> 2, c4 = ci & 3;
    const int t = (blk / 9) * 4 + c4;
    const int r = tid >> 2;
    const int s2 = (tid & 3);
    const int hg = (qt1 + (blk / 3) % 3) * 8 + (r >> 3);
    const int wg = (qt2 + blk % 3) * 8 + (r & 7);
    const long g = (long)(t * 40 + hg) * 64 + wg;
    const char* ks = (const char*)(kbase + g * 128) + s2 * 64;
    const char* vs = (const char*)(vbase + g * 128) + s2 * 64;
    const uint32_t ka = kd_base + (uint32_t)r * PITCH + (uint32_t)s2 * 64u;
    const uint32_t va = vd_base + (uint32_t)r * PITCH + (uint32_t)s2 * 64u;
    #pragma unroll
    for (int f = 0; f < 4; ++f) cp16(ka + f * 16u, ks + f * 16);
    #pragma unroll
    for (int f = 0; f < 4; ++f) cp16(va + f * 16u, vs + f * 16);
}

__global__ __launch_bounds__(256, 1)
void sta_attn8(float* __restrict__ out) {
    extern __shared__ char smem[];
    const uint32_t sb = smem_u32(smem);
    const int tid = threadIdx.x, warp = tid >> 5, lane = tid & 31;
    const int head = blockIdx.y;
    const int qb = blockIdx.x;
    const int qt0 = qb / 18, qt1 = (qb / 6) % 3, qt2 = qb % 6;
    const __half* kbase = g_kpk + (long)head * 30720 * 128;
    const __half* vbase = g_vpk + (long)head * 30720 * 128;

    // ---- stage Q via cp.async (prepacked), 1 row/thread ----
    {
        const int r = tid;
        const int a = r >> 6, b = (r >> 3) & 7, c = r & 7;
        const int t = qt0 * 4 + a, hh = qt1 * 8 + b, ww = qt2 * 8 + c;
        const long l = ((long)(t * 24 + hh)) * 48 + ww;
        const char* src = (const char*)(g_qpk + ((long)head * 13824 + l) * 128);
        const uint32_t dst = sb + QS_B + (uint32_t)r * PITCH;
        #pragma unroll
        for (int f = 0; f < 16; ++f) cp16(dst + f * 16u, src + f * 16);
    }
    // ---- prefetch chunks 0,1 ----
    stage_async(sb + KS_B, sb + VS_B, kbase, vbase, qt1, qt2, 0, tid);
    CP_COMMIT();                                   // {Q, chunk0}
    stage_async(sb + KS_B + KVSTRIDE, sb + VS_B + KVSTRIDE, kbase, vbase, qt1, qt2, 1, tid);
    CP_COMMIT();                                   // {chunk1}
    CP_WAIT(1);
    __syncthreads();

    // accumulators: warp owns q-rows [32*warp, 32*warp+32)
    float o0[16][4], o1[16][4];
    #pragma unroll
    for (int i = 0; i < 16; ++i) {
        o0[i][0]=0.f; o0[i][1]=0.f; o0[i][2]=0.f; o0[i][3]=0.f;
        o1[i][0]=0.f; o1[i][1]=0.f; o1[i][2]=0.f; o1[i][3]=0.f;
    }
    float lf0[4] = {0.f,0.f,0.f,0.f}, lf1[4] = {0.f,0.f,0.f,0.f};

    const uint32_t qb0 = sb + QS_B +
        (uint32_t)(warp * 32 + (lane & 15)) * PITCH + (uint32_t)(lane >> 4) * 16u;
    const uint32_t qb1 = qb0 + 16u * PITCH;
    const uint32_t kRow = (uint32_t)((((lane >> 4) & 1) * 8 + (lane & 7)) * PITCH
                                     + ((lane >> 3) & 1) * 16);
    const uint32_t vRow = (uint32_t)(((((lane >> 3) & 1) * 8) + (lane & 7)) * PITCH
                                     + (lane >> 4) * 16);

    #pragma unroll 1
    for (int i = 0; i < 108; ++i) {
        const uint32_t mr = (uint32_t)(i % 3) * KVSTRIDE;
        const uint32_t ksb = sb + KS_B + mr + kRow;
        const uint32_t vsb = sb + VS_B + mr + vRow;

        // prefetch chunk i+2 into ring slot (i+2)%3
        if (i <= 105) {
            const uint32_t mw = (uint32_t)((i + 2) % 3) * KVSTRIDE;
            stage_async(sb + KS_B + mw, sb + VS_B + mw, kbase, vbase, qt1, qt2, i + 2, tid);
            CP_COMMIT();
        }

        // ---- S = Q x K^T : 32 rows x 64 keys, k=128 ----
        float s0[8][4], s1[8][4];
        #pragma unroll
        for (int nt = 0; nt < 8; ++nt) {
            s0[nt][0]=0.f; s0[nt][1]=0.f; s0[nt][2]=0.f; s0[nt][3]=0.f;
            s1[nt][0]=0.f; s1[nt][1]=0.f; s1[nt][2]=0.f; s1[nt][3]=0.f;
        }
        #pragma unroll
        for (int kk = 0; kk < 8; ++kk) {
            uint32_t q0[4], q1[4];
            ldsm_x4(q0[0], q0[1], q0[2], q0[3], qb0 + (uint32_t)kk * 32u);
            ldsm_x4(q1[0], q1[1], q1[2], q1[3], qb1 + (uint32_t)kk * 32u);
            #pragma unroll
            for (int n2 = 0; n2 < 4; ++n2) {
                uint32_t b0, b1, b2, b3;
                ldsm_x4(b0, b1, b2, b3, ksb + (uint32_t)n2 * (16u * PITCH) + (uint32_t)kk * 32u);
                mma_f16(s0[2*n2],   q0[0], q0[1], q0[2], q0[3], b0, b1);
                mma_f16(s0[2*n2+1], q0[0], q0[1], q0[2], q0[3], b2, b3);
                mma_f16(s1[2*n2],   q1[0], q1[1], q1[2], q1[3], b0, b1);
                mma_f16(s1[2*n2+1], q1[0], q1[1], q1[2], q1[3], b2, b3);
            }
        }

        // ---- softmax in f16x2; accumulator layout == A-fragment layout ----
        uint32_t pa0[4][4], pa1[4][4];
        #pragma unroll
        for (int nt = 0; nt < 8; ++nt) {
            pa0[nt >> 1][(nt & 1) * 2 + 0] = cvt_ex2(s0[nt][0], s0[nt][1]);
            pa0[nt >> 1][(nt & 1) * 2 + 1] = cvt_ex2(s0[nt][2], s0[nt][3]);
            pa1[nt >> 1][(nt & 1) * 2 + 0] = cvt_ex2(s1[nt][0], s1[nt][1]);
            pa1[nt >> 1][(nt & 1) * 2 + 1] = cvt_ex2(s1[nt][2], s1[nt][3]);
        }
        // row-sums via ones-MMA
        #pragma unroll
        for (int kk = 0; kk < 4; ++kk) {
            mma_f16(lf0, pa0[kk][0], pa0[kk][1], pa0[kk][2], pa0[kk][3], ONESH2, ONESH2);
            mma_f16(lf1, pa1[kk][0], pa1[kk][1], pa1[kk][2], pa1[kk][3], ONESH2, ONESH2);
        }

        // ---- O += P x V ----
        #pragma unroll
        for (int kk = 0; kk < 4; ++kk) {
            #pragma unroll
            for (int n2 = 0; n2 < 8; ++n2) {
                uint32_t b0, b1, b2, b3;
                ldsm_x4t(b0, b1, b2, b3, vsb + (uint32_t)kk * (16u * PITCH) + (uint32_t)n2 * 32u);
                mma_f16(o0[2*n2],   pa0[kk][0], pa0[kk][1], pa0[kk][2], pa0[kk][3], b0, b1);
                mma_f16(o0[2*n2+1], pa0[kk][0], pa0[kk][1], pa0[kk][2], pa0[kk][3], b2, b3);
                mma_f16(o1[2*n2],   pa1[kk][0], pa1[kk][1], pa1[kk][2], pa1[kk][3], b0, b1);
                mma_f16(o1[2*n2+1], pa1[kk][0], pa1[kk][1], pa1[kk][2], pa1[kk][3], b2, b3);
            }
        }

        CP_WAIT(1);          // chunk i+1 landed
        __syncthreads();     // all warps done with slot i%3
    }

    // ---- epilogue ----
    const int g_ = lane >> 2, tig = lane & 3;
    #pragma unroll
    for (int hf = 0; hf < 2; ++hf) {
        const float inv0 = 1.0f / (hf ? lf1[0] : lf0[0]);
        const float inv1 = 1.0f / (hf ? lf1[2] : lf0[2]);
        #pragma unroll
        for (int rr = 0; rr < 2; ++rr) {
            const int qi = warp * 32 + hf * 16 + g_ + rr * 8;
            const int a = qi >> 6, b = (qi >> 3) & 7, c = qi & 7;
            const int t = qt0 * 4 + a, hh = qt1 * 8 + b, ww = qt2 * 8 + c;
            const long l = ((long)(t * 24 + hh)) * 48 + ww;
            float* dst = out + (l * NHEADS + head) * 128;
            const float inv = rr ? inv1 : inv0;
            #pragma unroll
            for (int nt = 0; nt < 16; ++nt) {
                float x0 = (hf ? o1 : o0)[nt][rr * 2 + 0] * inv;
                float x1 = (hf ? o1 : o0)[nt][rr * 2 + 1] * inv;
                *(float2*)(dst + nt * 8 + 2 * tig) = make_float2(x0, x1);
            }
        }
    }
}

extern "C" void kernel_launch(void* const* d_in, const int* in_sizes, int n_in,
                              void* d_out, int out_size) {
    const float* q = (const float*)d_in[0];
    const float* k = (const float*)d_in[1];
    const float* v = (const float*)d_in[2];
    float* out = (float*)d_out;

    rope_init_kernel<<<12, 256>>>();
    prepack_kv2<<<(int)(((long)NHEADS * 30720 * 32 + 255) / 256), 256>>>(k, v);
    prepack_q2<<<(int)(((long)NHEADS * 13824 * 32 + 255) / 256), 256>>>(q);

    cudaFuncSetAttribute(sta_attn8, cudaFuncAttributeMaxDynamicSharedMemorySize,
                         (int)SMEM_TOTAL);
    dim3 grid(54, NHEADS);
    sta_attn8<<<grid, 256, SMEM_TOTAL>>>(out);
}

// round 12
// speedup vs baseline: 1.3461x; 1.0328x over previous
#include <cuda_runtime.h>
#include <cuda_fp16.h>
#include <cstdint>

#define NHEADS 24

// ================= prepacked fp16 KV (glued canvas, roped K) =================
__device__ __half g_kpk[(long)NHEADS * 30720 * 128];   // [head][g][d]
__device__ __half g_vpk[(long)NHEADS * 30720 * 128];

// ================= RoPE tables =================
__device__ float2 g_rope_t[12 * 8];
__device__ float2 g_rope_h[40 * 28];
__device__ float2 g_rope_w[64 * 28];

__global__ void rope_init_kernel() {
    int idx = blockIdx.x * blockDim.x + threadIdx.x;
    if (idx < 96) {
        int p = idx >> 3, j = idx & 7;
        float ang = (float)p * exp2f(-(float)j);
        g_rope_t[idx] = make_float2(cosf(ang), sinf(ang));
    } else if (idx < 96 + 1120) {
        int r = idx - 96, i = r / 28, j = r % 28;
        float ang = (float)(i - 8) * exp2f(-8.0f * (float)j / 28.0f);
        g_rope_h[r] = make_float2(cosf(ang), sinf(ang));
    } else if (idx < 96 + 1120 + 1792) {
        int r = idx - 96 - 1120, i = r / 28, j = r % 28;
        float ang = (float)(i - 8) * exp2f(-8.0f * (float)j / 28.0f);
        g_rope_w[r] = make_float2(cosf(ang), sinf(ang));
    }
}

__device__ __forceinline__ float2 rope_pair(int pt, int ih, int iw, int j) {
    if (j < 8)  return g_rope_t[pt * 8 + j];
    if (j < 36) return g_rope_h[ih * 28 + (j - 8)];
    return g_rope_w[iw * 28 + (j - 36)];
}

__device__ __forceinline__ uint32_t packh2(float lo, float hi) {
    __half2 h = __floats2half2_rn(lo, hi);
    return *(uint32_t*)&h;
}

// ---- coalesced prepack KV: thread = (glued row, 4-dim slice) ----
__global__ void prepack_kv2(const float* __restrict__ k, const float* __restrict__ v) {
    const long idx = (long)blockIdx.x * 256 + threadIdx.x;   // row*32 + d4
    if (idx >= (long)NHEADS * 30720 * 32) return;
    const int d4 = (int)(idx & 31);
    const long row = idx >> 5;
    const int head = (int)(row % 24);
    const int g = (int)(row / 24);
    const int t = g / 2560, rem = g % 2560, hg = rem >> 6, wg = rem & 63;
    int hh = hg - 8; if (hh < 0) hh += 24; if (hh >= 24) hh -= 24;
    int ww = wg - 8; if (ww < 0) ww += 48; if (ww >= 48) ww -= 48;
    const long l = (long)(t * 24 + hh) * 48 + ww;
    const int d = d4 * 4;
    float4 x = *(const float4*)(k + (l * NHEADS + head) * 128 + d);
    float2 r0 = rope_pair(t, hg, wg, d >> 1);
    float2 r1 = rope_pair(t, hg, wg, (d >> 1) + 1);
    uint2 y;
    y.x = packh2(x.x * r0.x - x.y * r0.y, x.y * r0.x + x.x * r0.y);
    y.y = packh2(x.z * r1.x - x.w * r1.y, x.w * r1.x + x.z * r1.y);
    *(uint2*)((char*)(g_kpk + ((long)head * 30720 + g) * 128) + d * 2) = y;
    float4 xv = *(const float4*)(v + (l * NHEADS + head) * 128 + d);
    uint2 yv; yv.x = packh2(xv.x, xv.y); yv.y = packh2(xv.z, xv.w);
    *(uint2*)((char*)(g_vpk + ((long)head * 30720 + g) * 128) + d * 2) = yv;
}

// ================= main-kernel helpers =================
__device__ __forceinline__ uint32_t smem_u32(const void* p) {
    uint32_t a;
    asm("{ .reg .u64 t; cvta.to.shared.u64 t, %1; cvt.u32.u64 %0, t; }" : "=r"(a) : "l"(p));
    return a;
}
__device__ __forceinline__ uint32_t ex2h2(uint32_t s) {
    uint32_t r;
    asm("ex2.approx.f16x2 %0, %1;" : "=r"(r) : "r"(s));
    return r;
}
__device__ __forceinline__ void cp16(uint32_t dst, const void* src) {
    asm volatile("cp.async.cg.shared.global [%0], [%1], 16;" :: "r"(dst), "l"(src));
}
#define CP_COMMIT() asm volatile("cp.async.commit_group;" ::: "memory")
#define CP_WAIT(n)  asm volatile("cp.async.wait_group %0;" :: "n"(n) : "memory")

__device__ __forceinline__ void ldsm_x4(uint32_t& r0, uint32_t& r1, uint32_t& r2,
                                        uint32_t& r3, uint32_t addr) {
    asm volatile("ldmatrix.sync.aligned.m8n8.x4.shared.b16 {%0,%1,%2,%3}, [%4];"
        : "=r"(r0), "=r"(r1), "=r"(r2), "=r"(r3) : "r"(addr));
}
__device__ __forceinline__ void ldsm_x4t(uint32_t& r0, uint32_t& r1, uint32_t& r2,
                                         uint32_t& r3, uint32_t addr) {
    asm volatile("ldmatrix.sync.aligned.m8n8.x4.trans.shared.b16 {%0,%1,%2,%3}, [%4];"
        : "=r"(r0), "=r"(r1), "=r"(r2), "=r"(r3) : "r"(addr));
}
// f32-accumulator mma (PV + row-sums)
__device__ __forceinline__ void mma_f16(float* c,
                                        uint32_t a0, uint32_t a1, uint32_t a2, uint32_t a3,
                                        uint32_t b0, uint32_t b1) {
    asm volatile(
        "mma.sync.aligned.m16n8k16.row.col.f32.f16.f16.f32 "
        "{%0,%1,%2,%3}, {%4,%5,%6,%7}, {%8,%9}, {%0,%1,%2,%3};\n"
        : "+f"(c[0]), "+f"(c[1]), "+f"(c[2]), "+f"(c[3])
        : "r"(a0), "r"(a1), "r"(a2), "r"(a3), "r"(b0), "r"(b1));
}
// f16-accumulator mma (S matmul — 2x rate, packed D)
__device__ __forceinline__ void mma_f16h(uint32_t* c,
                                         uint32_t a0, uint32_t a1, uint32_t a2, uint32_t a3,
                                         uint32_t b0, uint32_t b1) {
    asm volatile(
        "mma.sync.aligned.m16n8k16.row.col.f16.f16.f16.f16 "
        "{%0,%1}, {%2,%3,%4,%5}, {%6,%7}, {%0,%1};\n"
        : "+r"(c[0]), "+r"(c[1])
        : "r"(a0), "r"(a1), "r"(a2), "r"(a3), "r"(b0), "r"(b1));
}

// ================= smem layout (bytes) =================
#define PITCH  272u
#define QS_B   0u            // 256 x 272 = 69632
#define KS_B   69632u        // 3 x (64 x 272)
#define VS_B   121856u       // 3 x (64 x 272)
#define KVSTRIDE 17408u
#define SMEM_TOTAL 174080u

#define ONESH2 0x3C003C00u

// stage one 64-key chunk via cp.async: 4 threads/row, 64B each
__device__ __forceinline__ void stage_async(uint32_t kd_base, uint32_t vd_base,
                                            const __half* kbase, const __half* vbase,
                                            int qt1, int qt2, int ci, int tid) {
    const int blk = ci >> 2, c4 = ci & 3;
    const int t = (blk / 9) * 4 + c4;
    const int r = tid >> 2;
    const int s2 = (tid & 3);
    const int hg = (qt1 + (blk / 3) % 3) * 8 + (r >> 3);
    const int wg = (qt2 + blk % 3) * 8 + (r & 7);
    const long g = (long)(t * 40 + hg) * 64 + wg;
    const char* ks = (const char*)(kbase + g * 128) + s2 * 64;
    const char* vs = (const char*)(vbase + g * 128) + s2 * 64;
    const uint32_t ka = kd_base + (uint32_t)r * PITCH + (uint32_t)s2 * 64u;
    const uint32_t va = vd_base + (uint32_t)r * PITCH + (uint32_t)s2 * 64u;
    #pragma unroll
    for (int f = 0; f < 4; ++f) cp16(ka + f * 16u, ks + f * 16);
    #pragma unroll
    for (int f = 0; f < 4; ++f) cp16(va + f * 16u, vs + f * 16);
}

__global__ __launch_bounds__(256, 1)
void sta_attn9(const float* __restrict__ q, float* __restrict__ out) {
    extern __shared__ char smem[];
    const uint32_t sb = smem_u32(smem);
    const int tid = threadIdx.x, warp = tid >> 5, lane = tid & 31;
    const int head = blockIdx.y;
    const int qb = blockIdx.x;
    const int qt0 = qb / 18, qt1 = (qb / 6) % 3, qt2 = qb % 6;
    const float QSCALE = 0.088388347648318447f * 1.4426950408889634f;
    const __half* kbase = g_kpk + (long)head * 30720 * 128;
    const __half* vbase = g_vpk + (long)head * 30720 * 128;

    // ---- stage Q inline (rope + scale -> fp16), 1 row/thread ----
    {
        const int r = tid;
        const int a = r >> 6, b = (r >> 3) & 7, c = r & 7;
        const int t = qt0 * 4 + a, hh = qt1 * 8 + b, ww = qt2 * 8 + c;
        const long l = ((long)(t * 24 + hh)) * 48 + ww;
        const float* src = q + (l * NHEADS + head) * 128;
        const int ih = hh + 8, iw = ww + 8;
        char* qrow = smem + QS_B + (uint32_t)r * PITCH;
        #pragma unroll
        for (int f = 0; f < 32; ++f) {
            const int d = f * 4;
            float4 x = *(const float4*)(src + d);
            float2 r0 = rope_pair(t, ih, iw, d >> 1);
            float2 r1 = rope_pair(t, ih, iw, (d >> 1) + 1);
            uint2 y;
            y.x = packh2((x.x * r0.x - x.y * r0.y) * QSCALE,
                         (x.y * r0.x + x.x * r0.y) * QSCALE);
            y.y = packh2((x.z * r1.x - x.w * r1.y) * QSCALE,
                         (x.w * r1.x + x.z * r1.y) * QSCALE);
            *(uint2*)(qrow + d * 2) = y;
        }
    }
    // ---- prefetch chunks 0,1 ----
    stage_async(sb + KS_B, sb + VS_B, kbase, vbase, qt1, qt2, 0, tid);
    CP_COMMIT();
    stage_async(sb + KS_B + KVSTRIDE, sb + VS_B + KVSTRIDE, kbase, vbase, qt1, qt2, 1, tid);
    CP_COMMIT();
    CP_WAIT(1);
    __syncthreads();

    // accumulators: warp owns q-rows [32*warp, 32*warp+32)
    float o0[16][4], o1[16][4];
    #pragma unroll
    for (int i = 0; i < 16; ++i) {
        o0[i][0]=0.f; o0[i][1]=0.f; o0[i][2]=0.f; o0[i][3]=0.f;
        o1[i][0]=0.f; o1[i][1]=0.f; o1[i][2]=0.f; o1[i][3]=0.f;
    }
    float lf0[4] = {0.f,0.f,0.f,0.f}, lf1[4] = {0.f,0.f,0.f,0.f};

    const uint32_t qb0 = sb + QS_B +
        (uint32_t)(warp * 32 + (lane & 15)) * PITCH + (uint32_t)(lane >> 4) * 16u;
    const uint32_t qb1 = qb0 + 16u * PITCH;
    const uint32_t kRow = (uint32_t)((((lane >> 4) & 1) * 8 + (lane & 7)) * PITCH
                                     + ((lane >> 3) & 1) * 16);
    const uint32_t vRow = (uint32_t)(((((lane >> 3) & 1) * 8) + (lane & 7)) * PITCH
                                     + (lane >> 4) * 16);

    #pragma unroll 1
    for (int i = 0; i < 108; ++i) {
        const uint32_t mr = (uint32_t)(i % 3) * KVSTRIDE;
        const uint32_t ksb = sb + KS_B + mr + kRow;
        const uint32_t vsb = sb + VS_B + mr + vRow;

        // prefetch chunk i+2 into ring slot (i+2)%3
        if (i <= 105) {
            const uint32_t mw = (uint32_t)((i + 2) % 3) * KVSTRIDE;
            stage_async(sb + KS_B + mw, sb + VS_B + mw, kbase, vbase, qt1, qt2, i + 2, tid);
            CP_COMMIT();
        }

        // ---- S = Q x K^T : 32 rows x 64 keys, k=128 (f16 accumulate, 2x rate) ----
        uint32_t s0[8][2], s1[8][2];
        #pragma unroll
        for (int nt = 0; nt < 8; ++nt) {
            s0[nt][0]=0u; s0[nt][1]=0u;
            s1[nt][0]=0u; s1[nt][1]=0u;
        }
        #pragma unroll
        for (int kk = 0; kk < 8; ++kk) {
            uint32_t q0[4], q1[4];
            ldsm_x4(q0[0], q0[1], q0[2], q0[3], qb0 + (uint32_t)kk * 32u);
            ldsm_x4(q1[0], q1[1], q1[2], q1[3], qb1 + (uint32_t)kk * 32u);
            #pragma unroll
            for (int n2 = 0; n2 < 4; ++n2) {
                uint32_t b0, b1, b2, b3;
                ldsm_x4(b0, b1, b2, b3, ksb + (uint32_t)n2 * (16u * PITCH) + (uint32_t)kk * 32u);
                mma_f16h(s0[2*n2],   q0[0], q0[1], q0[2], q0[3], b0, b1);
                mma_f16h(s0[2*n2+1], q0[0], q0[1], q0[2], q0[3], b2, b3);
                mma_f16h(s1[2*n2],   q1[0], q1[1], q1[2], q1[3], b0, b1);
                mma_f16h(s1[2*n2+1], q1[0], q1[1], q1[2], q1[3], b2, b3);
            }
        }

        // ---- softmax: D fragment is already packed f16x2 A-layout; just exp2 ----
        uint32_t pa0[4][4], pa1[4][4];
        #pragma unroll
        for (int nt = 0; nt < 8; ++nt) {
            pa0[nt >> 1][(nt & 1) * 2 + 0] = ex2h2(s0[nt][0]);   // rows g
            pa0[nt >> 1][(nt & 1) * 2 + 1] = ex2h2(s0[nt][1]);   // rows g+8
            pa1[nt >> 1][(nt & 1) * 2 + 0] = ex2h2(s1[nt][0]);
            pa1[nt >> 1][(nt & 1) * 2 + 1] = ex2h2(s1[nt][1]);
        }
        // row-sums via ones-MMA (f32 acc)
        #pragma unroll
        for (int kk = 0; kk < 4; ++kk) {
            mma_f16(lf0, pa0[kk][0], pa0[kk][1], pa0[kk][2], pa0[kk][3], ONESH2, ONESH2);
            mma_f16(lf1, pa1[kk][0], pa1[kk][1], pa1[kk][2], pa1[kk][3], ONESH2, ONESH2);
        }

        // ---- O += P x V (f32 acc) ----
        #pragma unroll
        for (int kk = 0; kk < 4; ++kk) {
            #pragma unroll
            for (int n2 = 0; n2 < 8; ++n2) {
                uint32_t b0, b1, b2, b3;
                ldsm_x4t(b0, b1, b2, b3, vsb + (uint32_t)kk * (16u * PITCH) + (uint32_t)n2 * 32u);
                mma_f16(o0[2*n2],   pa0[kk][0], pa0[kk][1], pa0[kk][2], pa0[kk][3], b0, b1);
                mma_f16(o0[2*n2+1], pa0[kk][0], pa0[kk][1], pa0[kk][2], pa0[kk][3], b2, b3);
                mma_f16(o1[2*n2],   pa1[kk][0], pa1[kk][1], pa1[kk][2], pa1[kk][3], b0, b1);
                mma_f16(o1[2*n2+1], pa1[kk][0], pa1[kk][1], pa1[kk][2], pa1[kk][3], b2, b3);
            }
        }

        CP_WAIT(1);          // chunk i+1 landed
        __syncthreads();     // all warps done with slot i%3
    }

    // ---- epilogue ----
    const int g_ = lane >> 2, tig = lane & 3;
    #pragma unroll
    for (int hf = 0; hf < 2; ++hf) {
        const float inv0 = 1.0f / (hf ? lf1[0] : lf0[0]);
        const float inv1 = 1.0f / (hf ? lf1[2] : lf0[2]);
        #pragma unroll
        for (int rr = 0; rr < 2; ++rr) {
            const int qi = warp * 32 + hf * 16 + g_ + rr * 8;
            const int a = qi >> 6, b = (qi >> 3) & 7, c = qi & 7;
            const int t = qt0 * 4 + a, hh = qt1 * 8 + b, ww = qt2 * 8 + c;
            const long l = ((long)(t * 24 + hh)) * 48 + ww;
            float* dst = out + (l * NHEADS + head) * 128;
            const float inv = rr ? inv1 : inv0;
            #pragma unroll
            for (int nt = 0; nt < 16; ++nt) {
                float x0 = (hf ? o1 : o0)[nt][rr * 2 + 0] * inv;
                float x1 = (hf ? o1 : o0)[nt][rr * 2 + 1] * inv;
                *(float2*)(dst + nt * 8 + 2 * tig) = make_float2(x0, x1);
            }
        }
    }
}

extern "C" void kernel_launch(void* const* d_in, const int* in_sizes, int n_in,
                              void* d_out, int out_size) {
    const float* q = (const float*)d_in[0];
    const float* k = (const float*)d_in[1];
    const float* v = (const float*)d_in[2];
    float* out = (float*)d_out;

    rope_init_kernel<<<12, 256>>>();
    prepack_kv2<<<(int)(((long)NHEADS * 30720 * 32 + 255) / 256), 256>>>(k, v);

    cudaFuncSetAttribute(sta_attn9, cudaFuncAttributeMaxDynamicSharedMemorySize,
                         (int)SMEM_TOTAL);
    dim3 grid(54, NHEADS);
    sta_attn9<<<grid, 256, SMEM_TOTAL>>>(q, out);
}